// round 3
// baseline (speedup 1.0000x reference)
#include <cuda_runtime.h>
#include <math_constants.h>

// RoIPool: input (N=2, C=256, H=50, W=50) f32, rois (K=256, 5) f32
// output (K, C, 7, 7) f32. spatial_scale = 0.0625, P = 7.
//
// R3: hoist per-ROI bin-bound computation into shared memory (once per
// block) instead of recomputing it in all 3.2M threads. 4 blocks per ROI
// for occupancy/balance; element order inside a block keeps (ph,pw)
// fastest so stores are coalesced and gathers keep row locality.

#define P 7
#define C_DIM 256
#define H_DIM 50
#define W_DIM 50
#define SCALE 0.0625f
#define BLOCKS_PER_ROI 4
#define ELEMS (C_DIM * P * P)          // 12544 outputs per ROI
#define PER_BLOCK (ELEMS / BLOCKS_PER_ROI)  // 3136

__global__ __launch_bounds__(256) void roipool_kernel(const float* __restrict__ x,
                                                      const float* __restrict__ rois,
                                                      float* __restrict__ out)
{
    const int k    = blockIdx.x >> 2;
    const int part = blockIdx.x & 3;

    __shared__ int s_hs[P], s_he[P], s_ws[P], s_we[P];
    __shared__ int s_b;

    if (threadIdx.x < P) {
        const float* r = rois + k * 5;
        float x1 = rintf(r[1] * SCALE);
        float y1 = rintf(r[2] * SCALE);
        float x2 = rintf(r[3] * SCALE);
        float y2 = rintf(r[4] * SCALE);

        float bin_w = fmaxf(x2 - x1 + 1.0f, 1.0f) * (1.0f / P);
        float bin_h = fmaxf(y2 - y1 + 1.0f, 1.0f) * (1.0f / P);

        float p = (float)threadIdx.x;
        s_hs[threadIdx.x] = (int)fminf(fmaxf(floorf(p * bin_h) + y1, 0.0f), (float)H_DIM);
        s_he[threadIdx.x] = (int)fminf(fmaxf(ceilf((p + 1.0f) * bin_h) + y1, 0.0f), (float)H_DIM);
        s_ws[threadIdx.x] = (int)fminf(fmaxf(floorf(p * bin_w) + x1, 0.0f), (float)W_DIM);
        s_we[threadIdx.x] = (int)fminf(fmaxf(ceilf((p + 1.0f) * bin_w) + x1, 0.0f), (float)W_DIM);
        if (threadIdx.x == 0) s_b = (int)r[0];
    }
    __syncthreads();

    const float* base = x + (size_t)s_b * (C_DIM * H_DIM * W_DIM);
    float* out_k = out + (size_t)k * ELEMS;

    const int start = part * PER_BLOCK;
    const int end   = start + PER_BLOCK;

    for (int i = start + threadIdx.x; i < end; i += 256) {
        int pw = i % P;
        int t  = i / P;
        int ph = t % P;
        int c  = t / P;

        int hs = s_hs[ph], he = s_he[ph];
        int ws = s_ws[pw], we = s_we[pw];

        float m = 0.0f;  // empty bins -> 0
        if (he > hs && we > ws) {
            m = -CUDART_INF_F;
            const float* p0 = base + c * (H_DIM * W_DIM);
            for (int h = hs; h < he; ++h) {
                const float* row = p0 + h * W_DIM;
                for (int w = ws; w < we; ++w) {
                    m = fmaxf(m, row[w]);
                }
            }
        }
        out_k[i] = m;
    }
}

extern "C" void kernel_launch(void* const* d_in, const int* in_sizes, int n_in,
                              void* d_out, int out_size)
{
    const float* x    = (const float*)d_in[0];
    const float* rois = (const float*)d_in[1];
    float* out        = (float*)d_out;

    // K = out_size / (C * P * P)
    int K = out_size / ELEMS;
    roipool_kernel<<<K * BLOCKS_PER_ROI, 256>>>(x, rois, out);
}

// round 4
// speedup vs baseline: 1.2897x; 1.2897x over previous
#include <cuda_runtime.h>
#include <math_constants.h>

// RoIPool: input (N=2, C=256, H=50, W=50) f32, rois (K=256, 5) f32
// output (K, C, 7, 7) f32. spatial_scale = 0.0625, P = 7.
//
// R4: one thread per output element (R2 mapping, full grid = 12544 blocks)
// AND per-block ROI-setup hoisting (R3 idea). Each block covers exactly
// 256 consecutive outputs of one ROI (49 blocks per ROI), so bin bounds
// are computed once per block by 7 threads into smem; the other threads
// pay only 4 LDS broadcasts instead of ~40 ALU ops of setup.

#define P 7
#define C_DIM 256
#define H_DIM 50
#define W_DIM 50
#define SCALE 0.0625f
#define ELEMS (C_DIM * P * P)   // 12544 per ROI
#define BLOCKS_PER_ROI (ELEMS / 256)  // 49

__global__ __launch_bounds__(256) void roipool_kernel(const float* __restrict__ x,
                                                      const float* __restrict__ rois,
                                                      float* __restrict__ out)
{
    // blockIdx.x = k * 49 + part
    const int k    = blockIdx.x / BLOCKS_PER_ROI;
    const int part = blockIdx.x - k * BLOCKS_PER_ROI;

    __shared__ int s_hs[P], s_he[P], s_ws[P], s_we[P];
    __shared__ int s_b;

    if (threadIdx.x < P) {
        const float* r = rois + k * 5;
        float x1 = rintf(r[1] * SCALE);
        float y1 = rintf(r[2] * SCALE);
        float x2 = rintf(r[3] * SCALE);
        float y2 = rintf(r[4] * SCALE);

        float bin_w = fmaxf(x2 - x1 + 1.0f, 1.0f) * (1.0f / P);
        float bin_h = fmaxf(y2 - y1 + 1.0f, 1.0f) * (1.0f / P);

        float p = (float)threadIdx.x;
        s_hs[threadIdx.x] = (int)fminf(fmaxf(floorf(p * bin_h) + y1, 0.0f), (float)H_DIM);
        s_he[threadIdx.x] = (int)fminf(fmaxf(ceilf((p + 1.0f) * bin_h) + y1, 0.0f), (float)H_DIM);
        s_ws[threadIdx.x] = (int)fminf(fmaxf(floorf(p * bin_w) + x1, 0.0f), (float)W_DIM);
        s_we[threadIdx.x] = (int)fminf(fmaxf(ceilf((p + 1.0f) * bin_w) + x1, 0.0f), (float)W_DIM);
        if (threadIdx.x == 0) s_b = (int)r[0];
    }
    __syncthreads();

    const int i  = part * 256 + threadIdx.x;   // index within this ROI's 12544 outputs
    const int pw = i % P;
    const int t  = i / P;
    const int ph = t % P;
    const int c  = t / P;

    const int hs = s_hs[ph], he = s_he[ph];
    const int ws = s_ws[pw], we = s_we[pw];

    float m = 0.0f;  // empty bins -> 0
    if (he > hs && we > ws) {
        m = -CUDART_INF_F;
        const float* p0 = x + ((size_t)s_b * C_DIM + c) * (H_DIM * W_DIM);
        for (int h = hs; h < he; ++h) {
            const float* row = p0 + h * W_DIM;
            for (int w = ws; w < we; ++w) {
                m = fmaxf(m, row[w]);
            }
        }
    }
    out[(size_t)k * ELEMS + i] = m;
}

extern "C" void kernel_launch(void* const* d_in, const int* in_sizes, int n_in,
                              void* d_out, int out_size)
{
    const float* x    = (const float*)d_in[0];
    const float* rois = (const float*)d_in[1];
    float* out        = (float*)d_out;

    int K = out_size / ELEMS;   // 256
    roipool_kernel<<<K * BLOCKS_PER_ROI, 256>>>(x, rois, out);
}

// round 6
// speedup vs baseline: 1.3975x; 1.0835x over previous
#include <cuda_runtime.h>
#include <math_constants.h>

// RoIPool: input (N=2, C=256, H=50, W=50) f32, rois (K=256, 5) f32
// output (K, C, 7, 7) f32. spatial_scale = 0.0625, P = 7.
//
// R5: replace the variable-bound nested gather loop with a fully
// unrolled 4x4 predicated window (data bound: wh<=256px -> roi span
// <=18 cells -> bin span <= 4 cells/dim). 16 predicated LDG+FMAX per
// output: no branches, no warp divergence on trip counts, MLP~16.
// A dynamic fallback covers the (impossible-for-this-data) span>4 case.

#define P 7
#define C_DIM 256
#define H_DIM 50
#define W_DIM 50
#define SCALE 0.0625f
#define ELEMS (C_DIM * P * P)          // 12544 per ROI
#define BLOCKS_PER_ROI (ELEMS / 256)   // 49
#define SPAN 4

__global__ __launch_bounds__(256) void roipool_kernel(const float* __restrict__ x,
                                                      const float* __restrict__ rois,
                                                      float* __restrict__ out)
{
    const int k    = blockIdx.x / BLOCKS_PER_ROI;
    const int part = blockIdx.x - k * BLOCKS_PER_ROI;

    __shared__ int s_hs[P], s_he[P], s_ws[P], s_we[P];
    __shared__ int s_b;

    if (threadIdx.x < P) {
        const float* r = rois + k * 5;
        float x1 = rintf(r[1] * SCALE);
        float y1 = rintf(r[2] * SCALE);
        float x2 = rintf(r[3] * SCALE);
        float y2 = rintf(r[4] * SCALE);

        float bin_w = fmaxf(x2 - x1 + 1.0f, 1.0f) * (1.0f / P);
        float bin_h = fmaxf(y2 - y1 + 1.0f, 1.0f) * (1.0f / P);

        float p = (float)threadIdx.x;
        s_hs[threadIdx.x] = (int)fminf(fmaxf(floorf(p * bin_h) + y1, 0.0f), (float)H_DIM);
        s_he[threadIdx.x] = (int)fminf(fmaxf(ceilf((p + 1.0f) * bin_h) + y1, 0.0f), (float)H_DIM);
        s_ws[threadIdx.x] = (int)fminf(fmaxf(floorf(p * bin_w) + x1, 0.0f), (float)W_DIM);
        s_we[threadIdx.x] = (int)fminf(fmaxf(ceilf((p + 1.0f) * bin_w) + x1, 0.0f), (float)W_DIM);
        if (threadIdx.x == 0) s_b = (int)r[0];
    }
    __syncthreads();

    const int i  = part * 256 + threadIdx.x;   // index within this ROI's 12544 outputs
    const int pw = i % P;
    const int t  = i / P;
    const int ph = t % P;
    const int c  = t / P;

    const int hs = s_hs[ph], he = s_he[ph];
    const int ws = s_ws[pw], we = s_we[pw];

    const float* p0 = x + ((size_t)s_b * C_DIM + c) * (H_DIM * W_DIM);

    // Fixed 4x4 predicated window; predicated-off LDGs issue no memory access.
    float m = -CUDART_INF_F;
    #pragma unroll
    for (int dh = 0; dh < SPAN; ++dh) {
        const int  h   = hs + dh;
        const bool hok = (h < he);
        const float* row = p0 + h * W_DIM;
        #pragma unroll
        for (int dw = 0; dw < SPAN; ++dw) {
            const int w = ws + dw;
            if (hok && (w < we)) m = fmaxf(m, row[w]);
        }
    }

    // Correctness-preserving fallback for spans > SPAN (not hit by this data).
    if (he - hs > SPAN || we - ws > SPAN) {
        m = -CUDART_INF_F;
        for (int h = hs; h < he; ++h) {
            const float* row = p0 + h * W_DIM;
            for (int w = ws; w < we; ++w) m = fmaxf(m, row[w]);
        }
    }

    const bool valid = (he > hs) && (we > ws);
    out[(size_t)k * ELEMS + i] = valid ? m : 0.0f;
}

extern "C" void kernel_launch(void* const* d_in, const int* in_sizes, int n_in,
                              void* d_out, int out_size)
{
    const float* x    = (const float*)d_in[0];
    const float* rois = (const float*)d_in[1];
    float* out        = (float*)d_out;

    int K = out_size / ELEMS;   // 256
    roipool_kernel<<<K * BLOCKS_PER_ROI, 256>>>(x, rois, out);
}

// round 7
// speedup vs baseline: 1.8158x; 1.2993x over previous
#include <cuda_runtime.h>
#include <math_constants.h>

// RoIPool: input (N=2, C=256, H=50, W=50) f32, rois (K=256, 5) f32
// output (K, C, 7, 7) f32. scale = 0.0625, P = 7.
//
// R6: channel vectorization. One thread computes CPT=4 channels of the
// same (k, ph, pw): window bounds / predicates / base address computed
// once, then 4x16 predicated LDGs whose addresses are all base+immediate
// (channel stride 2500 floats, window offsets dh*50+dw). Amortizes the
// ALU/issue overhead that dominated R5 (alu=54%) by ~4x.

#define P 7
#define C_DIM 256
#define H_DIM 50
#define W_DIM 50
#define HW (H_DIM * W_DIM)
#define SCALE 0.0625f
#define ELEMS (C_DIM * P * P)      // 12544 outputs per ROI
#define CPT 4                      // channels per thread
#define WORK_PER_ROI (ELEMS / CPT) // 3136 work items per ROI
#define BLOCKS_PER_ROI 13          // 13*256 = 3328 >= 3136
#define SPAN 4

__global__ __launch_bounds__(256) void roipool_kernel(const float* __restrict__ x,
                                                      const float* __restrict__ rois,
                                                      float* __restrict__ out)
{
    const int k    = blockIdx.x / BLOCKS_PER_ROI;
    const int part = blockIdx.x - k * BLOCKS_PER_ROI;

    __shared__ int s_hs[P], s_he[P], s_ws[P], s_we[P];
    __shared__ int s_b;

    if (threadIdx.x < P) {
        const float* r = rois + k * 5;
        float x1 = rintf(r[1] * SCALE);
        float y1 = rintf(r[2] * SCALE);
        float x2 = rintf(r[3] * SCALE);
        float y2 = rintf(r[4] * SCALE);

        float bin_w = fmaxf(x2 - x1 + 1.0f, 1.0f) * (1.0f / P);
        float bin_h = fmaxf(y2 - y1 + 1.0f, 1.0f) * (1.0f / P);

        float p = (float)threadIdx.x;
        s_hs[threadIdx.x] = (int)fminf(fmaxf(floorf(p * bin_h) + y1, 0.0f), (float)H_DIM);
        s_he[threadIdx.x] = (int)fminf(fmaxf(ceilf((p + 1.0f) * bin_h) + y1, 0.0f), (float)H_DIM);
        s_ws[threadIdx.x] = (int)fminf(fmaxf(floorf(p * bin_w) + x1, 0.0f), (float)W_DIM);
        s_we[threadIdx.x] = (int)fminf(fmaxf(ceilf((p + 1.0f) * bin_w) + x1, 0.0f), (float)W_DIM);
        if (threadIdx.x == 0) s_b = (int)rois[k * 5];
    }
    __syncthreads();

    const int i = part * 256 + threadIdx.x;   // work item within this ROI
    if (i >= WORK_PER_ROI) return;

    // i -> (channel group, position). pos fastest so lane-adjacent threads
    // write contiguous outputs within a channel tile.
    const int cg  = i / (P * P);              // 0..63
    const int pos = i - cg * (P * P);         // 0..48
    const int ph  = pos / P;
    const int pw  = pos - ph * P;

    const int hs = s_hs[ph], he = s_he[ph];
    const int ws = s_ws[pw], we = s_we[pw];
    const bool valid = (he > hs) && (we > ws);

    const float* base = x + ((size_t)s_b * C_DIM + cg * CPT) * HW + hs * W_DIM + ws;

    float m[CPT];
    #pragma unroll
    for (int ch = 0; ch < CPT; ++ch) m[ch] = -CUDART_INF_F;

    // Fixed 4x4 predicated window, shared predicates across CPT channels.
    #pragma unroll
    for (int dh = 0; dh < SPAN; ++dh) {
        const bool hok = (hs + dh < he);
        #pragma unroll
        for (int dw = 0; dw < SPAN; ++dw) {
            const bool ok = hok && (ws + dw < we);
            #pragma unroll
            for (int ch = 0; ch < CPT; ++ch) {
                if (ok) m[ch] = fmaxf(m[ch], base[ch * HW + dh * W_DIM + dw]);
            }
        }
    }

    // Correctness-preserving fallback for spans > SPAN (not hit by this data).
    if (he - hs > SPAN || we - ws > SPAN) {
        #pragma unroll
        for (int ch = 0; ch < CPT; ++ch) m[ch] = -CUDART_INF_F;
        for (int h = 0; h < he - hs; ++h) {
            for (int w = 0; w < we - ws; ++w) {
                #pragma unroll
                for (int ch = 0; ch < CPT; ++ch) {
                    m[ch] = fmaxf(m[ch], base[ch * HW + h * W_DIM + w]);
                }
            }
        }
    }

    float* o = out + (size_t)k * ELEMS + cg * (CPT * P * P) + pos;
    #pragma unroll
    for (int ch = 0; ch < CPT; ++ch) {
        o[ch * (P * P)] = valid ? m[ch] : 0.0f;
    }
}

extern "C" void kernel_launch(void* const* d_in, const int* in_sizes, int n_in,
                              void* d_out, int out_size)
{
    const float* x    = (const float*)d_in[0];
    const float* rois = (const float*)d_in[1];
    float* out        = (float*)d_out;

    int K = out_size / ELEMS;   // 256
    roipool_kernel<<<K * BLOCKS_PER_ROI, 256>>>(x, rois, out);
}